// round 2
// baseline (speedup 1.0000x reference)
#include <cuda_runtime.h>

#define EPS 1e-5f
#define NB 512
#define NF 300
#define NP 361      // 19*19 positions
#define WP 20       // padded w dimension

// ---------------- static device scratch (no allocation allowed) ----------------
__device__ float g_Wcomb[288 * 256];        // combined layer-1 weights: 256 NDI + 16 (-wr) + 16 (+wc)
__device__ float g_w2t[256 * 128];          // w2 transposed [c][o]
__device__ float g_w3t[128 * 64];           // w3 transposed [c][o]
__device__ float g_w4t[64 * 4];             // w4 transposed [c][o]
__device__ float g_gbuf[NB * NP * 128];     // layer-2 activations ("g"), ~94.6 MB
__device__ float g_mbuf[NB * NP * 4];       // layer-4 logits

// ---------------- prep kernel: weight repack ----------------
__global__ void prep_kernel(const float* __restrict__ w1, const float* __restrict__ w2,
                            const float* __restrict__ w3, const float* __restrict__ w4) {
    int idx = blockIdx.x * blockDim.x + threadIdx.x;
    int stride = gridDim.x * blockDim.x;

    // Reference: DI[a,c] = xp[c] - xp[a] = v_j - u_i  (channel (i,j): a=i*19+h, c=j*19+w)
    // Sum over even channels: sum_{ij} (v_j - u_i) w_even[o,i,j]
    //   = sum_j v_j * wc[o,j]  -  sum_i u_i * wr[o,i]
    // Wcomb[k][o]:
    //  k <  256 : NDI weight  w1[o, i*32 + j*2 + 1], i=k>>4, j=k&15 (N holds (v-u)/(u+v+eps))
    //  256..271 : -wr[o,i] = -sum_j w1[o, i*32 + j*2]     (N holds u_i)
    //  272..287 : +wc[o,j] = +sum_i w1[o, i*32 + j*2]     (N holds v_j)
    for (int t = idx; t < 288 * 256; t += stride) {
        int k = t >> 8, o = t & 255;
        float v;
        if (k < 256) {
            int i = k >> 4, j = k & 15;
            v = w1[o * 512 + i * 32 + j * 2 + 1];
        } else if (k < 272) {
            int i = k - 256;
            float s = 0.f;
            #pragma unroll
            for (int j = 0; j < 16; j++) s += w1[o * 512 + i * 32 + j * 2];
            v = -s;
        } else {
            int j = k - 272;
            float s = 0.f;
            #pragma unroll
            for (int i = 0; i < 16; i++) s += w1[o * 512 + i * 32 + j * 2];
            v = s;
        }
        g_Wcomb[k * 256 + o] = v;
    }
    for (int t = idx; t < 256 * 128; t += stride) {
        int k = t >> 7, o = t & 127;
        g_w2t[t] = w2[o * 256 + k];
    }
    for (int t = idx; t < 128 * 64; t += stride) {
        int k = t >> 6, o = t & 63;
        g_w3t[t] = w3[o * 128 + k];
    }
    for (int t = idx; t < 256; t += stride) {
        int c = t >> 2, oh = t & 3;
        g_w4t[t] = w4[oh * 64 + c];
    }
}

// ---------------- main fused MLP kernel: one block per (b, h) ----------------
__global__ __launch_bounds__(320) void mlp_kernel(const float* __restrict__ x,
                                                  const float* __restrict__ b1,
                                                  const float* __restrict__ b2,
                                                  const float* __restrict__ b3,
                                                  const float* __restrict__ b4) {
    extern __shared__ float sm[];
    float* s_xp = sm;                  // 304 padded input row
    float* s_N  = sm + 304;            // 288 * WP  "channel matrix"
    float* s_h1 = s_N + 288 * WP;      // 256 * WP
    float* s_h2 = s_h1 + 256 * WP;     // 128 * WP
    float* s_m3 = s_N;                 // alias (N dead after layer 1), 64 * WP

    const int b = blockIdx.x;
    const int h = blockIdx.y;
    const int tid = threadIdx.x;

    // padded input row xp[b, 0..303]  (pad 2 each side)
    if (tid < 304) {
        float v = 0.f;
        if (tid >= 2 && tid < 302) v = x[b * NF + tid - 2];
        s_xp[tid] = v;
    }
    __syncthreads();

    // Build N[k][w]:
    //  k<256: NDI_{ij}(w) = (v_j - u_i) / (u_i + v_j + eps), u_i = xp[i*19+h], v_j = xp[j*19+w]
    //  256..271: u_i (weighted by -wr);  272..287: v_j (weighted by +wc)
    for (int idx = tid; idx < 288 * WP; idx += 320) {
        int k = idx / WP, w = idx - k * WP;
        float val = 0.f;
        if (w < 19) {
            if (k < 256) {
                int i = k >> 4, j = k & 15;
                float u = s_xp[i * 19 + h];
                float v = s_xp[j * 19 + w];
                val = __fdividef(v - u, u + v + EPS);
            } else if (k < 272) {
                val = s_xp[(k - 256) * 19 + h];
            } else {
                val = s_xp[(k - 272) * 19 + w];
            }
        }
        s_N[idx] = val;
    }
    __syncthreads();

    // -------- layer 1: 288-contraction -> 256, leaky --------
    {
        const int ox = tid & 63, wx = tid >> 6;   // 64 o-groups x 5 w-groups
        const int o0 = ox * 4, w0 = wx * 4;
        float acc[4][4];
        #pragma unroll
        for (int oo = 0; oo < 4; oo++) {
            float bb = b1[o0 + oo];
            #pragma unroll
            for (int wi = 0; wi < 4; wi++) acc[wi][oo] = bb;
        }
        #pragma unroll 4
        for (int k = 0; k < 288; k++) {
            float4 nv = *(const float4*)(s_N + k * WP + w0);
            float4 wv = *(const float4*)(g_Wcomb + k * 256 + o0);
            acc[0][0] += nv.x * wv.x; acc[0][1] += nv.x * wv.y; acc[0][2] += nv.x * wv.z; acc[0][3] += nv.x * wv.w;
            acc[1][0] += nv.y * wv.x; acc[1][1] += nv.y * wv.y; acc[1][2] += nv.y * wv.z; acc[1][3] += nv.y * wv.w;
            acc[2][0] += nv.z * wv.x; acc[2][1] += nv.z * wv.y; acc[2][2] += nv.z * wv.z; acc[2][3] += nv.z * wv.w;
            acc[3][0] += nv.w * wv.x; acc[3][1] += nv.w * wv.y; acc[3][2] += nv.w * wv.z; acc[3][3] += nv.w * wv.w;
        }
        #pragma unroll
        for (int wi = 0; wi < 4; wi++)
            #pragma unroll
            for (int oo = 0; oo < 4; oo++) {
                float v = acc[wi][oo];
                v = v >= 0.f ? v : 0.01f * v;
                s_h1[(o0 + oo) * WP + w0 + wi] = v;
            }
    }
    __syncthreads();

    // -------- layer 2: 256 -> 128, leaky; also emit g to global --------
    {
        const int ox = tid & 31, wx = tid >> 5;   // 32 o-groups x 10 w-groups
        const int o0 = ox * 4, w0 = wx * 2;
        float acc[2][4];
        #pragma unroll
        for (int oo = 0; oo < 4; oo++) {
            float bb = b2[o0 + oo];
            acc[0][oo] = bb; acc[1][oo] = bb;
        }
        #pragma unroll 4
        for (int k = 0; k < 256; k++) {
            float2 nv = *(const float2*)(s_h1 + k * WP + w0);
            float4 wv = *(const float4*)(g_w2t + k * 128 + o0);
            acc[0][0] += nv.x * wv.x; acc[0][1] += nv.x * wv.y; acc[0][2] += nv.x * wv.z; acc[0][3] += nv.x * wv.w;
            acc[1][0] += nv.y * wv.x; acc[1][1] += nv.y * wv.y; acc[1][2] += nv.y * wv.z; acc[1][3] += nv.y * wv.w;
        }
        #pragma unroll
        for (int wi = 0; wi < 2; wi++) {
            int w = w0 + wi;
            float4 ov;
            float* o4 = (float*)&ov;
            #pragma unroll
            for (int oo = 0; oo < 4; oo++) {
                float v = acc[wi][oo];
                v = v >= 0.f ? v : 0.01f * v;
                o4[oo] = v;
                s_h2[(o0 + oo) * WP + w] = v;
            }
            if (w < 19) {
                *(float4*)(g_gbuf + ((size_t)(b * NP + h * 19 + w)) * 128 + o0) = ov;
            }
        }
    }
    __syncthreads();

    // -------- layer 3: 128 -> 64, relu --------
    {
        const int ox = tid & 15, w = tid >> 4;    // 16 o-groups x 20 w
        const int o0 = ox * 4;
        float acc[4];
        #pragma unroll
        for (int oo = 0; oo < 4; oo++) acc[oo] = b3[o0 + oo];
        #pragma unroll 4
        for (int k = 0; k < 128; k++) {
            float nv = s_h2[k * WP + w];
            float4 wv = *(const float4*)(g_w3t + k * 64 + o0);
            acc[0] += nv * wv.x; acc[1] += nv * wv.y; acc[2] += nv * wv.z; acc[3] += nv * wv.w;
        }
        #pragma unroll
        for (int oo = 0; oo < 4; oo++) {
            float v = acc[oo];
            s_m3[(o0 + oo) * WP + w] = v > 0.f ? v : 0.f;
        }
    }
    __syncthreads();

    // -------- layer 4: 64 -> 4, relu, write logits --------
    if (tid < 76) {
        const int w = tid >> 2, oh = tid & 3;     // w in [0,19)
        float acc = b4[oh];
        #pragma unroll 8
        for (int c = 0; c < 64; c++) acc += s_m3[c * WP + w] * g_w4t[c * 4 + oh];
        acc = acc > 0.f ? acc : 0.f;
        g_mbuf[(b * NP + h * 19 + w) * 4 + oh] = acc;
    }
}

// ---------------- softmax over 361 positions + weighted reduction ----------------
__global__ __launch_bounds__(128) void softmax_kernel(float* __restrict__ out) {
    __shared__ float s_m[NP * 4];
    __shared__ float s_w[NP * 4];
    __shared__ float s_mx[4];
    __shared__ float s_iz[4];
    const int b = blockIdx.x;
    const int tid = threadIdx.x;

    for (int i = tid; i < NP * 4; i += 128) s_m[i] = g_mbuf[b * NP * 4 + i];
    __syncthreads();

    if (tid < 4) {
        float mx = -1e30f;
        for (int p = 0; p < NP; p++) mx = fmaxf(mx, s_m[p * 4 + tid]);
        s_mx[tid] = mx;
    }
    __syncthreads();

    for (int i = tid; i < NP * 4; i += 128) s_w[i] = __expf(s_m[i] - s_mx[i & 3]);
    __syncthreads();

    if (tid < 4) {
        float z = 0.f;
        for (int p = 0; p < NP; p++) z += s_w[p * 4 + tid];
        s_iz[tid] = __fdividef(1.f, z);
    }
    __syncthreads();

    const int head = tid >> 5;
    const float* gp = g_gbuf + (size_t)b * NP * 128 + tid;
    float acc = 0.f;
    #pragma unroll 4
    for (int p = 0; p < NP; p++) acc += s_w[p * 4 + head] * gp[(size_t)p * 128];
    out[b * 128 + tid] = acc * s_iz[head];
}

// ---------------- launch ----------------
extern "C" void kernel_launch(void* const* d_in, const int* in_sizes, int n_in,
                              void* d_out, int out_size) {
    const float* x  = (const float*)d_in[0];
    const float* w1 = (const float*)d_in[1];
    const float* b1 = (const float*)d_in[2];
    const float* w2 = (const float*)d_in[3];
    const float* b2 = (const float*)d_in[4];
    const float* w3 = (const float*)d_in[5];
    const float* b3 = (const float*)d_in[6];
    const float* w4 = (const float*)d_in[7];
    const float* b4 = (const float*)d_in[8];
    float* out = (float*)d_out;

    const int smem_bytes = (304 + 288 * WP + 256 * WP + 128 * WP) * sizeof(float); // 54976
    cudaFuncSetAttribute(mlp_kernel, cudaFuncAttributeMaxDynamicSharedMemorySize, smem_bytes);

    prep_kernel<<<128, 256>>>(w1, w2, w3, w4);
    mlp_kernel<<<dim3(NB, 19), 320, smem_bytes>>>(x, b1, b2, b3, b4);
    softmax_kernel<<<NB, 128>>>(out);
}

// round 3
// speedup vs baseline: 1.0549x; 1.0549x over previous
#include <cuda_runtime.h>

#define EPS 1e-5f
#define NB 512
#define NF 300
#define NP 361      // 19*19 positions
#define WP 24       // padded w row stride (16B-aligned rows)

typedef unsigned long long ull;

// ---------------- static device scratch (no allocation allowed) ----------------
__device__ float g_Wcomb[288 * 256];        // combined layer-1 weights: 256 NDI + 16 (-wr) + 16 (+wc)
__device__ float g_w2t[256 * 128];          // w2 transposed [c][o]
__device__ float g_w3t[128 * 64];           // w3 transposed [c][o]
__device__ float g_w4t[64 * 4];             // w4 transposed [c][o]
__device__ float g_gbuf[NB * NP * 128];     // layer-2 activations ("g"), ~94.6 MB
__device__ float g_mbuf[NB * NP * 4];       // layer-4 logits

// ---------------- f32x2 packed helpers ----------------
__device__ __forceinline__ void ffma2(ull& d, ull a, ull b) {
    asm("fma.rn.f32x2 %0, %1, %2, %0;" : "+l"(d) : "l"(a), "l"(b));
}
__device__ __forceinline__ ull dup2(float v) {
    ull r; asm("mov.b64 %0, {%1, %1};" : "=l"(r) : "f"(v)); return r;
}
__device__ __forceinline__ void unpack2(ull p, float& lo, float& hi) {
    asm("mov.b64 {%0, %1}, %2;" : "=f"(lo), "=f"(hi) : "l"(p));
}
__device__ __forceinline__ float leaky(float v) { return v >= 0.f ? v : 0.01f * v; }
__device__ __forceinline__ float relu(float v)  { return v > 0.f ? v : 0.f; }

// Load 5 packed activation pairs (10 consecutive floats at row+WX*10), aligned forms.
template<int WX>
__device__ __forceinline__ void load5(const float* row, ull& p0, ull& p1, ull& p2, ull& p3, ull& p4) {
    if (WX == 0) {
        ulonglong2 A = *(const ulonglong2*)(row);      // floats 0..3
        ulonglong2 B = *(const ulonglong2*)(row + 4);  // floats 4..7
        ull        C = *(const ull*)(row + 8);         // floats 8..9
        p0 = A.x; p1 = A.y; p2 = B.x; p3 = B.y; p4 = C;
    } else {
        ull        A = *(const ull*)(row);             // floats 10..11 (byte 40, 8B aligned)
        ulonglong2 B = *(const ulonglong2*)(row + 2);  // floats 12..15 (byte 48)
        ulonglong2 C = *(const ulonglong2*)(row + 6);  // floats 16..19 (byte 64)
        p0 = A; p1 = B.x; p2 = B.y; p3 = C.x; p4 = C.y;
    }
}

// ---------------- prep kernel: weight repack ----------------
__global__ void prep_kernel(const float* __restrict__ w1, const float* __restrict__ w2,
                            const float* __restrict__ w3, const float* __restrict__ w4) {
    int idx = blockIdx.x * blockDim.x + threadIdx.x;
    int stride = gridDim.x * blockDim.x;

    // DI[a,c] = xp[c] - xp[a] = v_j - u_i  (channel (i,j): a=i*19+h, c=j*19+w)
    // Wcomb[k][o]:
    //  k <  256 : NDI weight  w1[o, i*32 + j*2 + 1], i=k>>4, j=k&15
    //  256..271 : -wr[o,i] = -sum_j w1[o, i*32 + j*2]     (N holds u_i)
    //  272..287 : +wc[o,j] = +sum_i w1[o, i*32 + j*2]     (N holds v_j)
    for (int t = idx; t < 288 * 256; t += stride) {
        int k = t >> 8, o = t & 255;
        float v;
        if (k < 256) {
            int i = k >> 4, j = k & 15;
            v = w1[o * 512 + i * 32 + j * 2 + 1];
        } else if (k < 272) {
            int i = k - 256;
            float s = 0.f;
            #pragma unroll
            for (int j = 0; j < 16; j++) s += w1[o * 512 + i * 32 + j * 2];
            v = -s;
        } else {
            int j = k - 272;
            float s = 0.f;
            #pragma unroll
            for (int i = 0; i < 16; i++) s += w1[o * 512 + i * 32 + j * 2];
            v = s;
        }
        g_Wcomb[k * 256 + o] = v;
    }
    for (int t = idx; t < 256 * 128; t += stride) {
        int k = t >> 7, o = t & 127;
        g_w2t[t] = w2[o * 256 + k];
    }
    for (int t = idx; t < 128 * 64; t += stride) {
        int k = t >> 6, o = t & 63;
        g_w3t[t] = w3[o * 128 + k];
    }
    for (int t = idx; t < 256; t += stride) {
        int c = t >> 2, oh = t & 3;
        g_w4t[t] = w4[oh * 64 + c];
    }
}

// ---------------- main fused MLP kernel: one block per (b, h) ----------------
__global__ __launch_bounds__(256) void mlp_kernel(const float* __restrict__ x,
                                                  const float* __restrict__ b1,
                                                  const float* __restrict__ b2,
                                                  const float* __restrict__ b3,
                                                  const float* __restrict__ b4) {
    extern __shared__ float sm[];
    float* s_xp = sm;                  // 320 padded input row (zero tail)
    float* s_N  = sm + 320;            // 288 * WP
    float* s_h1 = s_N + 288 * WP;      // 256 * WP
    float* s_h2 = s_h1 + 256 * WP;     // 128 * WP
    float* s_m3 = s_N;                 // alias (N dead after layer 1), 64 * WP

    const int b = blockIdx.x;
    const int h = blockIdx.y;
    const int tid = threadIdx.x;

    // padded input row xp[b, 0..303] (pad 2 each side), zero through 319
    for (int i = tid; i < 320; i += 256) {
        float v = 0.f;
        if (i >= 2 && i < 302) v = x[b * NF + i - 2];
        s_xp[i] = v;
    }
    __syncthreads();

    // Build N[k][w] for w in [0,20):
    //  k<256: NDI_{ij}(w) = (v_j - u_i) / (u_i + v_j + eps), u_i = xp[i*19+h], v_j = xp[j*19+w]
    //  256..271: u_i (weight -wr);  272..287: v_j (weight +wc)
    for (int idx = tid; idx < 288 * 20; idx += 256) {
        int k = idx / 20, w = idx - k * 20;
        float val;
        if (k < 256) {
            int i = k >> 4, j = k & 15;
            float u = s_xp[i * 19 + h];
            float v = s_xp[j * 19 + w];
            val = __fdividef(v - u, u + v + EPS);
        } else if (k < 272) {
            val = s_xp[(k - 256) * 19 + h];
        } else {
            val = s_xp[(k - 272) * 19 + w];
        }
        s_N[k * WP + w] = val;
    }
    __syncthreads();

    // -------- layer 1: 288 -> 256, leaky. tile: 2 o x 10 w, acc packed over w --------
    {
        const int ox = tid & 127, wx = tid >> 7;
        const int o0 = ox * 2, w0 = wx * 10;
        ull a0[5], a1[5];
        {
            ull bb0 = dup2(b1[o0]), bb1 = dup2(b1[o0 + 1]);
            #pragma unroll
            for (int i = 0; i < 5; i++) { a0[i] = bb0; a1[i] = bb1; }
        }
        const float* np = s_N + w0;
        const float* wp = g_Wcomb + o0;
        if (wx == 0) {
            #pragma unroll 2
            for (int k = 0; k < 288; k++) {
                ull p0, p1, p2, p3, p4;
                load5<0>(np + k * WP, p0, p1, p2, p3, p4);
                float2 wv = *(const float2*)(wp + k * 256);
                ull d0 = dup2(wv.x), d1 = dup2(wv.y);
                ffma2(a0[0], p0, d0); ffma2(a0[1], p1, d0); ffma2(a0[2], p2, d0); ffma2(a0[3], p3, d0); ffma2(a0[4], p4, d0);
                ffma2(a1[0], p0, d1); ffma2(a1[1], p1, d1); ffma2(a1[2], p2, d1); ffma2(a1[3], p3, d1); ffma2(a1[4], p4, d1);
            }
        } else {
            #pragma unroll 2
            for (int k = 0; k < 288; k++) {
                ull p0, p1, p2, p3, p4;
                load5<1>(np + k * WP, p0, p1, p2, p3, p4);
                float2 wv = *(const float2*)(wp + k * 256);
                ull d0 = dup2(wv.x), d1 = dup2(wv.y);
                ffma2(a0[0], p0, d0); ffma2(a0[1], p1, d0); ffma2(a0[2], p2, d0); ffma2(a0[3], p3, d0); ffma2(a0[4], p4, d0);
                ffma2(a1[0], p0, d1); ffma2(a1[1], p1, d1); ffma2(a1[2], p2, d1); ffma2(a1[3], p3, d1); ffma2(a1[4], p4, d1);
            }
        }
        #pragma unroll
        for (int oo = 0; oo < 2; oo++) {
            ull* acc = oo ? a1 : a0;
            float* dst = s_h1 + (o0 + oo) * WP + w0;
            #pragma unroll
            for (int i = 0; i < 5; i++) {
                float lo, hi; unpack2(acc[i], lo, hi);
                dst[2 * i]     = leaky(lo);
                dst[2 * i + 1] = leaky(hi);
            }
        }
    }
    __syncthreads();

    // -------- layer 2: 256 -> 128, leaky; emits g. 128 active threads, 2 o x 10 w --------
    if (tid < 128) {
        const int ox = tid & 63, wx = tid >> 6;
        const int o0 = ox * 2, w0 = wx * 10;
        ull a0[5], a1[5];
        {
            ull bb0 = dup2(b2[o0]), bb1 = dup2(b2[o0 + 1]);
            #pragma unroll
            for (int i = 0; i < 5; i++) { a0[i] = bb0; a1[i] = bb1; }
        }
        const float* np = s_h1 + w0;
        const float* wp = g_w2t + o0;
        if (wx == 0) {
            #pragma unroll 2
            for (int k = 0; k < 256; k++) {
                ull p0, p1, p2, p3, p4;
                load5<0>(np + k * WP, p0, p1, p2, p3, p4);
                float2 wv = *(const float2*)(wp + k * 128);
                ull d0 = dup2(wv.x), d1 = dup2(wv.y);
                ffma2(a0[0], p0, d0); ffma2(a0[1], p1, d0); ffma2(a0[2], p2, d0); ffma2(a0[3], p3, d0); ffma2(a0[4], p4, d0);
                ffma2(a1[0], p0, d1); ffma2(a1[1], p1, d1); ffma2(a1[2], p2, d1); ffma2(a1[3], p3, d1); ffma2(a1[4], p4, d1);
            }
        } else {
            #pragma unroll 2
            for (int k = 0; k < 256; k++) {
                ull p0, p1, p2, p3, p4;
                load5<1>(np + k * WP, p0, p1, p2, p3, p4);
                float2 wv = *(const float2*)(wp + k * 128);
                ull d0 = dup2(wv.x), d1 = dup2(wv.y);
                ffma2(a0[0], p0, d0); ffma2(a0[1], p1, d0); ffma2(a0[2], p2, d0); ffma2(a0[3], p3, d0); ffma2(a0[4], p4, d0);
                ffma2(a1[0], p0, d1); ffma2(a1[1], p1, d1); ffma2(a1[2], p2, d1); ffma2(a1[3], p3, d1); ffma2(a1[4], p4, d1);
            }
        }
        float v0[10], v1[10];
        #pragma unroll
        for (int i = 0; i < 5; i++) {
            float lo, hi;
            unpack2(a0[i], lo, hi); v0[2 * i] = leaky(lo); v0[2 * i + 1] = leaky(hi);
            unpack2(a1[i], lo, hi); v1[2 * i] = leaky(lo); v1[2 * i + 1] = leaky(hi);
        }
        float* dst0 = s_h2 + o0 * WP + w0;
        float* dst1 = dst0 + WP;
        #pragma unroll
        for (int i = 0; i < 10; i++) { dst0[i] = v0[i]; dst1[i] = v1[i]; }
        // g emit: g_gbuf[pos][o0..o0+1]
        const size_t posbase = (size_t)(b * NP + h * 19);
        #pragma unroll
        for (int i = 0; i < 10; i++) {
            int w = w0 + i;
            if (w < 19) {
                *(float2*)(g_gbuf + (posbase + w) * 128 + o0) = make_float2(v0[i], v1[i]);
            }
        }
    }
    __syncthreads();

    // -------- layer 3: 128 -> 64, relu. 64 active threads, 2 o x 10 w --------
    if (tid < 64) {
        const int ox = tid & 31, wx = tid >> 5;
        const int o0 = ox * 2, w0 = wx * 10;
        ull a0[5], a1[5];
        {
            ull bb0 = dup2(b3[o0]), bb1 = dup2(b3[o0 + 1]);
            #pragma unroll
            for (int i = 0; i < 5; i++) { a0[i] = bb0; a1[i] = bb1; }
        }
        const float* np = s_h2 + w0;
        const float* wp = g_w3t + o0;
        ull acc0[5], acc1[5];
        #pragma unroll
        for (int i = 0; i < 5; i++) { acc0[i] = a0[i]; acc1[i] = a1[i]; }
        if (wx == 0) {
            #pragma unroll 2
            for (int k = 0; k < 128; k++) {
                ull p0, p1, p2, p3, p4;
                load5<0>(np + k * WP, p0, p1, p2, p3, p4);
                float2 wv = *(const float2*)(wp + k * 64);
                ull d0 = dup2(wv.x), d1 = dup2(wv.y);
                ffma2(acc0[0], p0, d0); ffma2(acc0[1], p1, d0); ffma2(acc0[2], p2, d0); ffma2(acc0[3], p3, d0); ffma2(acc0[4], p4, d0);
                ffma2(acc1[0], p0, d1); ffma2(acc1[1], p1, d1); ffma2(acc1[2], p2, d1); ffma2(acc1[3], p3, d1); ffma2(acc1[4], p4, d1);
            }
        } else {
            #pragma unroll 2
            for (int k = 0; k < 128; k++) {
                ull p0, p1, p2, p3, p4;
                load5<1>(np + k * WP, p0, p1, p2, p3, p4);
                float2 wv = *(const float2*)(wp + k * 64);
                ull d0 = dup2(wv.x), d1 = dup2(wv.y);
                ffma2(acc0[0], p0, d0); ffma2(acc0[1], p1, d0); ffma2(acc0[2], p2, d0); ffma2(acc0[3], p3, d0); ffma2(acc0[4], p4, d0);
                ffma2(acc1[0], p0, d1); ffma2(acc1[1], p1, d1); ffma2(acc1[2], p2, d1); ffma2(acc1[3], p3, d1); ffma2(acc1[4], p4, d1);
            }
        }
        // NOTE: s_m3 aliases s_N, but s_N (layer-1 input) is dead; s_h2 (layer-3 input) is separate.
        float* dst0 = s_m3 + o0 * WP + w0;
        float* dst1 = dst0 + WP;
        #pragma unroll
        for (int i = 0; i < 5; i++) {
            float lo, hi;
            unpack2(acc0[i], lo, hi); dst0[2 * i] = relu(lo); dst0[2 * i + 1] = relu(hi);
            unpack2(acc1[i], lo, hi); dst1[2 * i] = relu(lo); dst1[2 * i + 1] = relu(hi);
        }
    }
    __syncthreads();

    // -------- layer 4: 64 -> 4, relu, write logits --------
    if (tid < 76) {
        const int w = tid >> 2, oh = tid & 3;     // w in [0,19)
        float acc = b4[oh];
        #pragma unroll 8
        for (int c = 0; c < 64; c++) acc += s_m3[c * WP + w] * g_w4t[c * 4 + oh];
        acc = relu(acc);
        g_mbuf[(b * NP + h * 19 + w) * 4 + oh] = acc;
    }
}

// ---------------- softmax over 361 positions + weighted reduction ----------------
__global__ __launch_bounds__(128) void softmax_kernel(float* __restrict__ out) {
    __shared__ float s_m[NP * 4];
    __shared__ float s_w[NP * 4];
    __shared__ float s_mx[4];
    __shared__ float s_iz[4];
    const int b = blockIdx.x;
    const int tid = threadIdx.x;

    for (int i = tid; i < NP * 4; i += 128) s_m[i] = g_mbuf[b * NP * 4 + i];
    __syncthreads();

    if (tid < 4) {
        float mx = -1e30f;
        for (int p = 0; p < NP; p++) mx = fmaxf(mx, s_m[p * 4 + tid]);
        s_mx[tid] = mx;
    }
    __syncthreads();

    for (int i = tid; i < NP * 4; i += 128) s_w[i] = __expf(s_m[i] - s_mx[i & 3]);
    __syncthreads();

    if (tid < 4) {
        float z = 0.f;
        for (int p = 0; p < NP; p++) z += s_w[p * 4 + tid];
        s_iz[tid] = __fdividef(1.f, z);
    }
    __syncthreads();

    const int head = tid >> 5;
    const float* gp = g_gbuf + (size_t)b * NP * 128 + tid;
    float acc = 0.f;
    #pragma unroll 4
    for (int p = 0; p < NP; p++) acc += s_w[p * 4 + head] * gp[(size_t)p * 128];
    out[b * 128 + tid] = acc * s_iz[head];
}

// ---------------- launch ----------------
extern "C" void kernel_launch(void* const* d_in, const int* in_sizes, int n_in,
                              void* d_out, int out_size) {
    const float* x  = (const float*)d_in[0];
    const float* w1 = (const float*)d_in[1];
    const float* b1 = (const float*)d_in[2];
    const float* w2 = (const float*)d_in[3];
    const float* b2 = (const float*)d_in[4];
    const float* w3 = (const float*)d_in[5];
    const float* b3 = (const float*)d_in[6];
    const float* w4 = (const float*)d_in[7];
    const float* b4 = (const float*)d_in[8];
    float* out = (float*)d_out;

    const int smem_bytes = (320 + (288 + 256 + 128) * WP) * sizeof(float); // 65792
    cudaFuncSetAttribute(mlp_kernel, cudaFuncAttributeMaxDynamicSharedMemorySize, smem_bytes);

    prep_kernel<<<128, 256>>>(w1, w2, w3, w4);
    mlp_kernel<<<dim3(NB, 19), 256, smem_bytes>>>(x, b1, b2, b3, b4);
    softmax_kernel<<<NB, 128>>>(out);
}

// round 4
// speedup vs baseline: 1.2595x; 1.1940x over previous
#include <cuda_runtime.h>

#define EPS 1e-5f
#define NB 512
#define NF 300
#define NP 361      // 19*19 positions
#define WP 20       // row stride in floats (80B, 16B-aligned)

typedef unsigned long long ull;

// ---------------- static device scratch (no allocation allowed) ----------------
__device__ float g_Wcomb[288 * 256];        // layer-1 combined: 256 NDI + 16 (-wr) + 16 (+wc)
__device__ float g_w2t[256 * 128];          // w2 transposed [c][o]
__device__ float g_w3t[128 * 64];           // w3 transposed [c][o]
__device__ float g_w4t[64 * 4];             // w4 transposed [c][o]
__device__ float g_gbuf[(size_t)NB * NP * 128];
__device__ float g_mbuf[NB * NP * 4];

// ---------------- f32x2 packed helpers ----------------
__device__ __forceinline__ void ffma2(ull& d, ull a, ull b) {
    asm("fma.rn.f32x2 %0, %1, %2, %0;" : "+l"(d) : "l"(a), "l"(b));
}
__device__ __forceinline__ ull dup2(float v) {
    ull r; asm("mov.b64 %0, {%1, %1};" : "=l"(r) : "f"(v)); return r;
}
__device__ __forceinline__ void unpack2(ull p, float& lo, float& hi) {
    asm("mov.b64 {%0, %1}, %2;" : "=f"(lo), "=f"(hi) : "l"(p));
}
__device__ __forceinline__ float leaky(float v) { return v >= 0.f ? v : 0.01f * v; }
__device__ __forceinline__ float relu(float v)  { return v > 0.f ? v : 0.f; }

// Load 5 packed pairs = 10 consecutive floats at row + (WX?10:0). WP=20 rows are 16B aligned.
template<int WX>
__device__ __forceinline__ void load5(const float* row, ull& p0, ull& p1, ull& p2, ull& p3, ull& p4) {
    if (WX == 0) {
        ulonglong2 A = *(const ulonglong2*)(row);      // 0..3   (16B @ 0)
        ulonglong2 B = *(const ulonglong2*)(row + 4);  // 4..7   (16B @ 16)
        ull        C = *(const ull*)(row + 8);         // 8..9   (8B  @ 32)
        p0 = A.x; p1 = A.y; p2 = B.x; p3 = B.y; p4 = C;
    } else {
        ull        A = *(const ull*)(row);             // 10..11 (8B  @ 40)
        ulonglong2 B = *(const ulonglong2*)(row + 2);  // 12..15 (16B @ 48)
        ulonglong2 C = *(const ulonglong2*)(row + 6);  // 16..19 (16B @ 64)
        p0 = A; p1 = B.x; p2 = B.y; p3 = C.x; p4 = C.y;
    }
}

// ---------------- per-chunk compute bodies ----------------
template<int WX>
__device__ __forceinline__ void l1_chunk(ull a[4][5], const float* nb, const float* wb) {
    #pragma unroll 4
    for (int r = 0; r < 16; ++r) {
        ull p0, p1, p2, p3, p4;
        load5<WX>(nb + r * WP, p0, p1, p2, p3, p4);
        float4 wv = *(const float4*)(wb + r * 256);
        ull d0 = dup2(wv.x), d1 = dup2(wv.y), d2 = dup2(wv.z), d3 = dup2(wv.w);
        ffma2(a[0][0], p0, d0); ffma2(a[0][1], p1, d0); ffma2(a[0][2], p2, d0); ffma2(a[0][3], p3, d0); ffma2(a[0][4], p4, d0);
        ffma2(a[1][0], p0, d1); ffma2(a[1][1], p1, d1); ffma2(a[1][2], p2, d1); ffma2(a[1][3], p3, d1); ffma2(a[1][4], p4, d1);
        ffma2(a[2][0], p0, d2); ffma2(a[2][1], p1, d2); ffma2(a[2][2], p2, d2); ffma2(a[2][3], p3, d2); ffma2(a[2][4], p4, d2);
        ffma2(a[3][0], p0, d3); ffma2(a[3][1], p1, d3); ffma2(a[3][2], p2, d3); ffma2(a[3][3], p3, d3); ffma2(a[3][4], p4, d3);
    }
}
template<int WX>
__device__ __forceinline__ void l2_chunk(ull a[2][5], const float* nb, const float* wb) {
    #pragma unroll 4
    for (int r = 0; r < 32; ++r) {
        ull p0, p1, p2, p3, p4;
        load5<WX>(nb + r * WP, p0, p1, p2, p3, p4);
        float2 wv = *(const float2*)(wb + r * 128);
        ull d0 = dup2(wv.x), d1 = dup2(wv.y);
        ffma2(a[0][0], p0, d0); ffma2(a[0][1], p1, d0); ffma2(a[0][2], p2, d0); ffma2(a[0][3], p3, d0); ffma2(a[0][4], p4, d0);
        ffma2(a[1][0], p0, d1); ffma2(a[1][1], p1, d1); ffma2(a[1][2], p2, d1); ffma2(a[1][3], p3, d1); ffma2(a[1][4], p4, d1);
    }
}
template<int WX>
__device__ __forceinline__ void l3_all(ull a[2][5], const float* nb, const float* wb) {
    #pragma unroll 4
    for (int k = 0; k < 128; ++k) {
        ull p0, p1, p2, p3, p4;
        load5<WX>(nb + k * WP, p0, p1, p2, p3, p4);
        float2 wv = *(const float2*)(wb + k * 64);
        ull d0 = dup2(wv.x), d1 = dup2(wv.y);
        ffma2(a[0][0], p0, d0); ffma2(a[0][1], p1, d0); ffma2(a[0][2], p2, d0); ffma2(a[0][3], p3, d0); ffma2(a[0][4], p4, d0);
        ffma2(a[1][0], p0, d1); ffma2(a[1][1], p1, d1); ffma2(a[1][2], p2, d1); ffma2(a[1][3], p3, d1); ffma2(a[1][4], p4, d1);
    }
}

// ---------------- prep kernel: weight repack ----------------
__global__ void prep_kernel(const float* __restrict__ w1, const float* __restrict__ w2,
                            const float* __restrict__ w3, const float* __restrict__ w4) {
    int idx = blockIdx.x * blockDim.x + threadIdx.x;
    int stride = gridDim.x * blockDim.x;
    for (int t = idx; t < 288 * 256; t += stride) {
        int k = t >> 8, o = t & 255;
        float v;
        if (k < 256) {
            int i = k >> 4, j = k & 15;
            v = w1[o * 512 + i * 32 + j * 2 + 1];
        } else if (k < 272) {
            int i = k - 256;
            float s = 0.f;
            #pragma unroll
            for (int j = 0; j < 16; j++) s += w1[o * 512 + i * 32 + j * 2];
            v = -s;
        } else {
            int j = k - 272;
            float s = 0.f;
            #pragma unroll
            for (int i = 0; i < 16; i++) s += w1[o * 512 + i * 32 + j * 2];
            v = s;
        }
        g_Wcomb[k * 256 + o] = v;
    }
    for (int t = idx; t < 256 * 128; t += stride) {
        int k = t >> 7, o = t & 127;
        g_w2t[t] = w2[o * 256 + k];
    }
    for (int t = idx; t < 128 * 64; t += stride) {
        int k = t >> 6, o = t & 63;
        g_w3t[t] = w3[o * 128 + k];
    }
    for (int t = idx; t < 256; t += stride) {
        int c = t >> 2, oh = t & 3;
        g_w4t[t] = w4[oh * 64 + c];
    }
}

// ---------------- main fused kernel: one block per (b, h-pair) ----------------
__global__ __launch_bounds__(256, 1) void mlp_kernel(const float* __restrict__ x,
                                                     const float* __restrict__ b1,
                                                     const float* __restrict__ b2,
                                                     const float* __restrict__ b3,
                                                     const float* __restrict__ b4) {
    extern __shared__ float sm[];
    float* s_xp = sm;                 // 320
    float* s_N  = sm + 320;           // 2 * 288 * 20 = 11520
    float* s_h1 = s_N + 11520;        // 2 * 256 * 20 = 10240
    float* s_h2 = s_h1 + 10240;       // 2 * 128 * 20 = 5120
    float* s_wb = s_h2 + 5120;        // 2 * 4096 weight staging
    // s_m3 aliases s_N (dead after layer 1): 2 * 64*20

    const int b  = blockIdx.x;
    const int h0 = blockIdx.y * 2;
    const int tid = threadIdx.x;

    // ---- prefetch W1 chunk 0 early (16 floats/thread) ----
    float4 pfa, pfb, pfc, pfd;
    {
        const float4* src = (const float4*)g_Wcomb;
        pfa = src[tid]; pfb = src[tid + 256]; pfc = src[tid + 512]; pfd = src[tid + 768];
    }

    // ---- padded input row ----
    for (int i = tid; i < 320; i += 256) {
        float v = 0.f;
        if (i >= 2 && i < 302) v = x[b * NF + i - 2];
        s_xp[i] = v;
    }
    __syncthreads();

    // ---- build N for both hh ----
    for (int e = tid; e < 11520; e += 256) {
        int hh = (e >= 5760);
        int idx = e - hh * 5760;
        int k = idx / WP, w = idx - k * WP;
        int h = h0 + hh;                     // h may be 19 (reads land in zero pad -> harmless)
        float val;
        if (k < 256) {
            int i = k >> 4, j = k & 15;
            float u = s_xp[i * 19 + h];
            float v = s_xp[j * 19 + w];
            val = __fdividef(v - u, u + v + EPS);
        } else if (k < 272) {
            val = s_xp[(k - 256) * 19 + h];
        } else {
            val = s_xp[(k - 272) * 19 + w];
        }
        s_N[e] = val;
    }
    // stage W1 chunk 0 into buf0
    {
        float4* dst = (float4*)s_wb;
        dst[tid] = pfa; dst[tid + 256] = pfb; dst[tid + 512] = pfc; dst[tid + 768] = pfd;
    }
    __syncthreads();

    // ---- thread tiling ----
    const int hh = tid >> 7;            // 0/1
    const int t  = tid & 127;
    const int wx = t >> 6;              // 0/1 -> w0 = 0/10
    const int w0 = wx * 10;
    const int hvalid = (h0 + hh) < 19;

    // ================= layer 1: 288 -> 256 (4o x 10w per thread) =================
    {
        const int o0 = (t & 63) * 4;
        const float* myN = s_N + hh * 5760 + w0;
        ull acc[4][5];
        {
            float4 bb = *(const float4*)(b1 + o0);
            ull i0 = dup2(bb.x), i1 = dup2(bb.y), i2 = dup2(bb.z), i3 = dup2(bb.w);
            #pragma unroll
            for (int i = 0; i < 5; i++) { acc[0][i] = i0; acc[1][i] = i1; acc[2][i] = i2; acc[3][i] = i3; }
        }
        for (int c = 0; c < 18; ++c) {
            // prefetch next chunk (or L2 chunk 0 on the last iter)
            float4 qa, qb, qc, qd;
            {
                const float4* s4 = (c < 17) ? (const float4*)(g_Wcomb + (c + 1) * 4096)
                                            : (const float4*)g_w2t;
                qa = s4[tid]; qb = s4[tid + 256]; qc = s4[tid + 512]; qd = s4[tid + 768];
            }
            const float* wb = s_wb + (c & 1) * 4096 + o0;
            const float* nb = myN + c * 16 * WP;
            if (wx == 0) l1_chunk<0>(acc, nb, wb);
            else         l1_chunk<1>(acc, nb, wb);
            {
                float4* dd = (float4*)(s_wb + ((c + 1) & 1) * 4096);
                dd[tid] = qa; dd[tid + 256] = qb; dd[tid + 512] = qc; dd[tid + 768] = qd;
            }
            __syncthreads();
        }
        // epilogue: leaky -> s_h1
        float* myH1 = s_h1 + hh * 5120 + w0;
        #pragma unroll
        for (int oo = 0; oo < 4; ++oo) {
            float* dst = myH1 + (o0 + oo) * WP;
            #pragma unroll
            for (int i = 0; i < 5; ++i) {
                float lo, hi; unpack2(acc[oo][i], lo, hi);
                dst[2 * i] = leaky(lo); dst[2 * i + 1] = leaky(hi);
            }
        }
    }
    __syncthreads();

    // ================= layer 2: 256 -> 128 (2o x 10w per thread) =================
    {
        const int o0 = (t & 63) * 2;
        const float* myH1 = s_h1 + hh * 5120 + w0;
        ull acc[2][5];
        {
            float2 bb = *(const float2*)(b2 + o0);
            ull i0 = dup2(bb.x), i1 = dup2(bb.y);
            #pragma unroll
            for (int i = 0; i < 5; i++) { acc[0][i] = i0; acc[1][i] = i1; }
        }
        for (int c = 0; c < 8; ++c) {
            float4 qa, qb, qc, qd;
            bool pf = (c < 7);
            if (pf) {
                const float4* s4 = (const float4*)(g_w2t + (c + 1) * 4096);
                qa = s4[tid]; qb = s4[tid + 256]; qc = s4[tid + 512]; qd = s4[tid + 768];
            }
            const float* wb = s_wb + (c & 1) * 4096 + o0;
            const float* nb = myH1 + c * 32 * WP;
            if (wx == 0) l2_chunk<0>(acc, nb, wb);
            else         l2_chunk<1>(acc, nb, wb);
            if (pf) {
                float4* dd = (float4*)(s_wb + ((c + 1) & 1) * 4096);
                dd[tid] = qa; dd[tid + 256] = qb; dd[tid + 512] = qc; dd[tid + 768] = qd;
            }
            __syncthreads();
        }
        // epilogue: leaky -> s_h2 and g_gbuf
        float v0[10], v1[10];
        #pragma unroll
        for (int i = 0; i < 5; ++i) {
            float lo, hi;
            unpack2(acc[0][i], lo, hi); v0[2 * i] = leaky(lo); v0[2 * i + 1] = leaky(hi);
            unpack2(acc[1][i], lo, hi); v1[2 * i] = leaky(lo); v1[2 * i + 1] = leaky(hi);
        }
        float* d0 = s_h2 + hh * 2560 + o0 * WP + w0;
        float* d1 = d0 + WP;
        #pragma unroll
        for (int i = 0; i < 10; ++i) { d0[i] = v0[i]; d1[i] = v1[i]; }
        if (hvalid) {
            const size_t posbase = (size_t)(b * NP + (h0 + hh) * 19);
            #pragma unroll
            for (int i = 0; i < 10; ++i) {
                int w = w0 + i;
                if (w < 19)
                    *(float2*)(g_gbuf + (posbase + w) * 128 + o0) = make_float2(v0[i], v1[i]);
            }
        }
    }
    __syncthreads();

    // ---- stage whole w3t (8192 floats) + w4t (256 floats into s_xp) ----
    {
        const float4* s4 = (const float4*)g_w3t;
        float4* d4 = (float4*)s_wb;
        #pragma unroll
        for (int q = 0; q < 8; ++q) d4[tid + q * 256] = s4[tid + q * 256];
        s_xp[tid] = g_w4t[tid];
    }
    __syncthreads();

    // ================= layer 3: 128 -> 64 (2o x 10w, 128 threads) =================
    if (tid < 128) {
        const int hh3 = tid >> 6, t3 = tid & 63;
        const int o0 = (t3 & 31) * 2;
        const int wx3 = t3 >> 5, w30 = wx3 * 10;
        const float* myH2 = s_h2 + hh3 * 2560 + w30;
        ull acc[2][5];
        {
            float2 bb = *(const float2*)(b3 + o0);
            ull i0 = dup2(bb.x), i1 = dup2(bb.y);
            #pragma unroll
            for (int i = 0; i < 5; i++) { acc[0][i] = i0; acc[1][i] = i1; }
        }
        if (wx3 == 0) l3_all<0>(acc, myH2, s_wb + o0);
        else          l3_all<1>(acc, myH2, s_wb + o0);
        float* m3 = s_N + hh3 * 1280;   // alias: s_N dead
        float* d0 = m3 + o0 * WP + w30;
        float* d1 = d0 + WP;
        #pragma unroll
        for (int i = 0; i < 5; ++i) {
            float lo, hi;
            unpack2(acc[0][i], lo, hi); d0[2 * i] = relu(lo); d0[2 * i + 1] = relu(hi);
            unpack2(acc[1][i], lo, hi); d1[2 * i] = relu(lo); d1[2 * i + 1] = relu(hi);
        }
    }
    __syncthreads();

    // ================= layer 4: 64 -> 4, logits =================
    if (tid < 152) {
        const int hh4 = (tid >= 76);
        const int tt = tid - hh4 * 76;
        const int w = tt >> 2, oh = tt & 3;
        const int h = h0 + hh4;
        const float* m3 = s_N + hh4 * 1280;
        float acc = b4[oh];
        #pragma unroll 8
        for (int c = 0; c < 64; ++c) acc += m3[c * WP + w] * s_xp[c * 4 + oh];
        if (h < 19) g_mbuf[(b * NP + h * 19 + w) * 4 + oh] = relu(acc);
    }
}

// ---------------- softmax over 361 positions + weighted reduction ----------------
__global__ __launch_bounds__(128) void softmax_kernel(float* __restrict__ out) {
    __shared__ float s_m[NP * 4];
    __shared__ float s_w[NP * 4];
    __shared__ float s_mx[4];
    __shared__ float s_iz[4];
    const int b = blockIdx.x;
    const int tid = threadIdx.x;

    for (int i = tid; i < NP * 4; i += 128) s_m[i] = g_mbuf[b * NP * 4 + i];
    __syncthreads();
    if (tid < 4) {
        float mx = -1e30f;
        for (int p = 0; p < NP; p++) mx = fmaxf(mx, s_m[p * 4 + tid]);
        s_mx[tid] = mx;
    }
    __syncthreads();
    for (int i = tid; i < NP * 4; i += 128) s_w[i] = __expf(s_m[i] - s_mx[i & 3]);
    __syncthreads();
    if (tid < 4) {
        float z = 0.f;
        for (int p = 0; p < NP; p++) z += s_w[p * 4 + tid];
        s_iz[tid] = __fdividef(1.f, z);
    }
    __syncthreads();
    const int head = tid >> 5;
    const float* gp = g_gbuf + (size_t)b * NP * 128 + tid;
    float acc = 0.f;
    #pragma unroll 4
    for (int p = 0; p < NP; p++) acc += s_w[p * 4 + head] * gp[(size_t)p * 128];
    out[b * 128 + tid] = acc * s_iz[head];
}

// ---------------- launch ----------------
extern "C" void kernel_launch(void* const* d_in, const int* in_sizes, int n_in,
                              void* d_out, int out_size) {
    const float* x  = (const float*)d_in[0];
    const float* w1 = (const float*)d_in[1];
    const float* b1 = (const float*)d_in[2];
    const float* w2 = (const float*)d_in[3];
    const float* b2 = (const float*)d_in[4];
    const float* w3 = (const float*)d_in[5];
    const float* b3 = (const float*)d_in[6];
    const float* w4 = (const float*)d_in[7];
    const float* b4 = (const float*)d_in[8];
    float* out = (float*)d_out;

    const int smem_bytes = (320 + 11520 + 10240 + 5120 + 8192) * sizeof(float); // 141568
    cudaFuncSetAttribute(mlp_kernel, cudaFuncAttributeMaxDynamicSharedMemorySize, smem_bytes);

    prep_kernel<<<128, 256>>>(w1, w2, w3, w4);
    mlp_kernel<<<dim3(NB, 10), 256, smem_bytes>>>(x, b1, b2, b3, b4);
    softmax_kernel<<<NB, 128>>>(out);
}